// round 5
// baseline (speedup 1.0000x reference)
#include <cuda_runtime.h>
#include <math.h>

// Problem shape (fixed by the dataset)
#define BATCH 16
#define SEQ   4096
#define HID   1024
#define KCHUNKS 16
#define KPER   (HID / KCHUNKS)   // 64
#define BLOCKS_PER_BATCH 512     // 4096 rows / 8 rows-per-block

// Scratch (no cudaMalloc allowed)
__device__ float g_u_part[KCHUNKS][HID];
__device__ float g_u[HID];
__device__ float g_energies[BATCH * SEQ];
__device__ int   g_ctr[BATCH];

// ---------------------------------------------------------------------------
// Kernel 1a: partial u over a k-chunk. grid = (HID/128, KCHUNKS), block = 128.
// ---------------------------------------------------------------------------
__global__ __launch_bounds__(128) void compute_u_part_kernel(
    const float* __restrict__ W, const float* __restrict__ v) {
    int h = blockIdx.x * 128 + threadIdx.x;
    int c = blockIdx.y;
    int k0 = c * KPER;
    const float* Wp = W + (size_t)k0 * (2 * HID) + HID + h;
    float acc = 0.0f;
#pragma unroll 8
    for (int k = 0; k < KPER; k++) {
        acc = fmaf(__ldg(v + k0 + k), __ldg(Wp + (size_t)k * (2 * HID)), acc);
    }
    g_u_part[c][h] = acc;
}

// ---------------------------------------------------------------------------
// Kernel 1b: reduce partials; also reset the last-block counters for this
// replay (runs before the energies kernel in the same stream every time).
// ---------------------------------------------------------------------------
__global__ __launch_bounds__(1024) void reduce_u_kernel() {
    int h = threadIdx.x;
    float acc = 0.0f;
#pragma unroll
    for (int c = 0; c < KCHUNKS; c++) acc += g_u_part[c][h];
    g_u[h] = acc;
    if (h < BATCH) g_ctr[h] = 0;
}

// ---------------------------------------------------------------------------
// Kernel 2: energies + fused last-block softmax.
// 8 rows per block (1 warp per row). Batch b owns blocks [b*512, (b+1)*512).
// The last block to finish a batch performs that batch's softmax — hidden
// behind the DRAM stream of later batches.
// ---------------------------------------------------------------------------
__global__ __launch_bounds__(256) void energies_softmax_kernel(
    const float* __restrict__ enc, float* __restrict__ out) {
    __shared__ float su[HID];
    __shared__ float red[8];
    __shared__ int s_last;

    int tid = threadIdx.x;
    for (int i = tid; i < HID; i += blockDim.x) su[i] = g_u[i];
    __syncthreads();

    int gwarp = (blockIdx.x * blockDim.x + tid) >> 5;  // row id
    int lane = tid & 31;
    int warp = tid >> 5;

    // ---- energies: dot(enc_row, u) ----
    {
        const float4* row = reinterpret_cast<const float4*>(enc + (size_t)gwarp * HID);
        const float4* uu = reinterpret_cast<const float4*>(su);
        float acc = 0.0f;
#pragma unroll
        for (int i = 0; i < HID / (32 * 4); i++) {  // 8 iterations
            float4 x = __ldcs(row + lane + i * 32);
            float4 u4 = uu[lane + i * 32];
            acc = fmaf(x.x, u4.x, acc);
            acc = fmaf(x.y, u4.y, acc);
            acc = fmaf(x.z, u4.z, acc);
            acc = fmaf(x.w, u4.w, acc);
        }
#pragma unroll
        for (int o = 16; o > 0; o >>= 1) acc += __shfl_xor_sync(0xFFFFFFFFu, acc, o);
        if (lane == 0) g_energies[gwarp] = acc;
    }
    __syncthreads();

    // ---- last-block election for this batch ----
    int b = blockIdx.x >> 9;  // / BLOCKS_PER_BATCH
    if (tid == 0) {
        __threadfence();  // publish our energies
        int old = atomicAdd(&g_ctr[b], 1);
        s_last = (old == BLOCKS_PER_BATCH - 1) ? 1 : 0;
    }
    __syncthreads();
    if (!s_last) return;
    __threadfence();  // acquire: see all batch-b energies

    // ---- softmax for batch b (256 threads, 16 floats each) ----
    const float4* e4 = reinterpret_cast<const float4*>(g_energies + (size_t)b * SEQ);
    float4* o4 = reinterpret_cast<float4*>(out + (size_t)b * SEQ);

    float4 x0 = e4[tid];
    float4 x1 = e4[tid + 256];
    float4 x2 = e4[tid + 512];
    float4 x3 = e4[tid + 768];

    float m = fmaxf(fmaxf(fmaxf(x0.x, x0.y), fmaxf(x0.z, x0.w)),
                    fmaxf(fmaxf(fmaxf(x1.x, x1.y), fmaxf(x1.z, x1.w)),
                          fmaxf(fmaxf(fmaxf(x2.x, x2.y), fmaxf(x2.z, x2.w)),
                                fmaxf(fmaxf(x3.x, x3.y), fmaxf(x3.z, x3.w)))));
#pragma unroll
    for (int of = 16; of > 0; of >>= 1) m = fmaxf(m, __shfl_xor_sync(~0u, m, of));
    if (lane == 0) red[warp] = m;
    __syncthreads();
    {
        float t = (lane < 8) ? red[lane] : -INFINITY;
#pragma unroll
        for (int of = 4; of > 0; of >>= 1) t = fmaxf(t, __shfl_xor_sync(~0u, t, of));
        m = __shfl_sync(~0u, t, 0);
    }

    x0.x = __expf(x0.x - m); x0.y = __expf(x0.y - m);
    x0.z = __expf(x0.z - m); x0.w = __expf(x0.w - m);
    x1.x = __expf(x1.x - m); x1.y = __expf(x1.y - m);
    x1.z = __expf(x1.z - m); x1.w = __expf(x1.w - m);
    x2.x = __expf(x2.x - m); x2.y = __expf(x2.y - m);
    x2.z = __expf(x2.z - m); x2.w = __expf(x2.w - m);
    x3.x = __expf(x3.x - m); x3.y = __expf(x3.y - m);
    x3.z = __expf(x3.z - m); x3.w = __expf(x3.w - m);

    float sum = (x0.x + x0.y + x0.z + x0.w) + (x1.x + x1.y + x1.z + x1.w)
              + (x2.x + x2.y + x2.z + x2.w) + (x3.x + x3.y + x3.z + x3.w);
#pragma unroll
    for (int of = 16; of > 0; of >>= 1) sum += __shfl_xor_sync(~0u, sum, of);
    __syncthreads();
    if (lane == 0) red[warp] = sum;
    __syncthreads();
    {
        float t = (lane < 8) ? red[lane] : 0.0f;
#pragma unroll
        for (int of = 4; of > 0; of >>= 1) t += __shfl_xor_sync(~0u, t, of);
        sum = __shfl_sync(~0u, t, 0);
    }

    float inv = __frcp_rn(sum);
    x0.x *= inv; x0.y *= inv; x0.z *= inv; x0.w *= inv;
    x1.x *= inv; x1.y *= inv; x1.z *= inv; x1.w *= inv;
    x2.x *= inv; x2.y *= inv; x2.z *= inv; x2.w *= inv;
    x3.x *= inv; x3.y *= inv; x3.z *= inv; x3.w *= inv;
    o4[tid] = x0;
    o4[tid + 256] = x1;
    o4[tid + 512] = x2;
    o4[tid + 768] = x3;
}

// ---------------------------------------------------------------------------
// Launch. Input order: hidden, encoder_outputs, W, b, v.
// hidden and b are mathematically dead (softmax shift invariance).
// ---------------------------------------------------------------------------
extern "C" void kernel_launch(void* const* d_in, const int* in_sizes, int n_in,
                              void* d_out, int out_size) {
    const float* enc = (const float*)d_in[1];
    const float* W = (const float*)d_in[2];
    const float* v = (const float*)d_in[4];
    float* out = (float*)d_out;

    compute_u_part_kernel<<<dim3(HID / 128, KCHUNKS), 128>>>(W, v);
    reduce_u_kernel<<<1, HID>>>();
    energies_softmax_kernel<<<BATCH * BLOCKS_PER_BATCH, 256>>>(enc, out);
}

// round 6
// speedup vs baseline: 1.0088x; 1.0088x over previous
#include <cuda_runtime.h>
#include <math.h>

// Problem shape (fixed by the dataset)
#define BATCH 16
#define SEQ   4096
#define HID   1024
#define KCHUNKS 64
#define KPER   (HID / KCHUNKS)   // 16

// Scratch (no cudaMalloc allowed)
__device__ float g_u_part[KCHUNKS][HID];
__device__ float g_u[HID];
__device__ float g_energies[BATCH * SEQ];

// ---------------------------------------------------------------------------
// Kernel 1a: partial u over a k-chunk. grid = (HID/128, KCHUNKS), block = 128.
// 512 blocks, KPER=16 fully unrolled -> 16 independent loads in flight/thread.
// ---------------------------------------------------------------------------
__global__ __launch_bounds__(128) void compute_u_part_kernel(
    const float* __restrict__ W, const float* __restrict__ v) {
    int h = blockIdx.x * 128 + threadIdx.x;
    int c = blockIdx.y;
    int k0 = c * KPER;
    const float* Wp = W + (size_t)k0 * (2 * HID) + HID + h;
    float acc = 0.0f;
#pragma unroll
    for (int k = 0; k < KPER; k++) {
        acc = fmaf(__ldg(v + k0 + k), __ldg(Wp + (size_t)k * (2 * HID)), acc);
    }
    g_u_part[c][h] = acc;
}

// ---------------------------------------------------------------------------
// Kernel 1b: reduce 64 partials. One block of 1024 threads; partials are
// L2-resident (256KB, just written).
// ---------------------------------------------------------------------------
__global__ __launch_bounds__(1024) void reduce_u_kernel() {
    int h = threadIdx.x;
    float acc = 0.0f;
#pragma unroll
    for (int c = 0; c < KCHUNKS; c++) acc += g_u_part[c][h];
    g_u[h] = acc;
}

// ---------------------------------------------------------------------------
// Kernel 2: energies[b,s] = dot(enc[b,s,:], u)   — the 256MB streaming pass.
// One warp per (b,s) row; u in shared; __ldcs (evict-first) on the stream.
// ---------------------------------------------------------------------------
__global__ __launch_bounds__(256) void energies_kernel(
    const float* __restrict__ enc) {
    __shared__ float su[HID];
    for (int i = threadIdx.x; i < HID; i += blockDim.x) su[i] = g_u[i];
    __syncthreads();

    int gwarp = (blockIdx.x * blockDim.x + threadIdx.x) >> 5;  // row id
    int lane = threadIdx.x & 31;

    const float4* row = reinterpret_cast<const float4*>(enc + (size_t)gwarp * HID);
    const float4* uu = reinterpret_cast<const float4*>(su);

    float acc = 0.0f;
#pragma unroll
    for (int i = 0; i < HID / (32 * 4); i++) {  // 8 iterations
        float4 x = __ldcs(row + lane + i * 32);
        float4 u4 = uu[lane + i * 32];
        acc = fmaf(x.x, u4.x, acc);
        acc = fmaf(x.y, u4.y, acc);
        acc = fmaf(x.z, u4.z, acc);
        acc = fmaf(x.w, u4.w, acc);
    }
#pragma unroll
    for (int o = 16; o > 0; o >>= 1) acc += __shfl_xor_sync(0xFFFFFFFFu, acc, o);
    if (lane == 0) g_energies[gwarp] = acc;
}

// ---------------------------------------------------------------------------
// Kernel 3: per-batch softmax. 1024 threads/block, one float4 per thread.
// Single global read + single global write; reductions register/smem-resident.
// ---------------------------------------------------------------------------
__global__ __launch_bounds__(1024) void softmax_kernel(float* __restrict__ out) {
    __shared__ float red[32];
    int tid = threadIdx.x;
    int lane = tid & 31;
    int warp = tid >> 5;

    const float4* e4 = reinterpret_cast<const float4*>(g_energies + (size_t)blockIdx.x * SEQ);
    float4* o4 = reinterpret_cast<float4*>(out + (size_t)blockIdx.x * SEQ);

    float4 x = e4[tid];

    // --- max ---
    float m = fmaxf(fmaxf(x.x, x.y), fmaxf(x.z, x.w));
#pragma unroll
    for (int of = 16; of > 0; of >>= 1) m = fmaxf(m, __shfl_xor_sync(~0u, m, of));
    if (lane == 0) red[warp] = m;
    __syncthreads();
    {
        float t = red[lane];  // 32 warps -> all lanes valid
#pragma unroll
        for (int of = 16; of > 0; of >>= 1) t = fmaxf(t, __shfl_xor_sync(~0u, t, of));
        m = t;
    }

    // --- exp + sum ---
    x.x = __expf(x.x - m);
    x.y = __expf(x.y - m);
    x.z = __expf(x.z - m);
    x.w = __expf(x.w - m);
    float sum = x.x + x.y + x.z + x.w;
#pragma unroll
    for (int of = 16; of > 0; of >>= 1) sum += __shfl_xor_sync(~0u, sum, of);
    __syncthreads();  // red reuse
    if (lane == 0) red[warp] = sum;
    __syncthreads();
    {
        float t = red[lane];
#pragma unroll
        for (int of = 16; of > 0; of >>= 1) t += __shfl_xor_sync(~0u, t, of);
        sum = t;
    }

    float inv = __frcp_rn(sum);
    x.x *= inv; x.y *= inv; x.z *= inv; x.w *= inv;
    o4[tid] = x;
}

// ---------------------------------------------------------------------------
// Launch. Input order: hidden, encoder_outputs, W, b, v.
// hidden and b are mathematically dead (softmax shift invariance).
// ---------------------------------------------------------------------------
extern "C" void kernel_launch(void* const* d_in, const int* in_sizes, int n_in,
                              void* d_out, int out_size) {
    const float* enc = (const float*)d_in[1];
    const float* W = (const float*)d_in[2];
    const float* v = (const float*)d_in[4];
    float* out = (float*)d_out;

    compute_u_part_kernel<<<dim3(HID / 128, KCHUNKS), 128>>>(W, v);
    reduce_u_kernel<<<1, HID>>>();
    energies_kernel<<<(BATCH * SEQ) / 8, 256>>>(enc);
    softmax_kernel<<<BATCH, 1024>>>(out);
}